// round 15
// baseline (speedup 1.0000x reference)
#include <cuda_runtime.h>

// out[row, t] = x[row, t - s]  if 0 <= t - s < T else 0
// rows = 256, T = 160000 (T % 4 == 0), s = shifts[row] - max_shift in [-16000, 16000]
//
// R14-best body (VEC=4 float4 words/thread, front-batched __ldcs loads,
// __stcs stores, interior fast path, full grid) with THREADS=1024: one more
// step along the block-size axis (the only axis still moving the needle,
// 256 -> 512 gave +0.5%). 64 KB contiguous read window per CTA for maximal
// DRAM page locality. Last tile per row (T4 % WPB != 0) takes the exact
// predicated path.

#define VEC 4
#define THREADS 1024
#define WPB (VEC * THREADS)   // 4096 float4 words = 16384 floats per tile

__global__ void __launch_bounds__(THREADS)
random_shift_kernel(const float* __restrict__ x,
                    const int* __restrict__ shifts,
                    float4* __restrict__ out4,
                    int T, int max_shift) {
    const int row = blockIdx.y;
    const int s = shifts[row] - max_shift;

    const int T4 = T >> 2;
    const int tile0 = blockIdx.x * WPB;                    // first word of tile
    const size_t ebase = (size_t)row * (size_t)T;          // element base
    const size_t wbase = (size_t)row * (size_t)T4;         // word base
    const float* __restrict__ xr = x + ebase;

    // tile source element range: [4*tile0 - s, 4*(tile0+WPB) - s)
    const int src_lo = 4 * tile0 - s;
    const int src_hi = 4 * (tile0 + WPB) - s;
    const bool interior = (src_lo >= 0) && (src_hi <= T) && (tile0 + WPB <= T4);

    float4 v[VEC];

    if (interior) {
#pragma unroll
        for (int k = 0; k < VEC; ++k) {
            const int u = 4 * (tile0 + (int)threadIdx.x + k * THREADS) - s;
            v[k].x = __ldcs(xr + u);
            v[k].y = __ldcs(xr + u + 1);
            v[k].z = __ldcs(xr + u + 2);
            v[k].w = __ldcs(xr + u + 3);
        }
#pragma unroll
        for (int k = 0; k < VEC; ++k) {
            const int w = tile0 + threadIdx.x + k * THREADS;
            __stcs(out4 + wbase + w, v[k]);
        }
    } else {
#pragma unroll
        for (int k = 0; k < VEC; ++k) {
            const int w = tile0 + threadIdx.x + k * THREADS;
            const int u = 4 * w - s;
            float t0 = 0.f, t1 = 0.f, t2 = 0.f, t3 = 0.f;
            if (w < T4) {
                if (u >= 0 && u + 3 < T) {
                    t0 = __ldcs(xr + u);
                    t1 = __ldcs(xr + u + 1);
                    t2 = __ldcs(xr + u + 2);
                    t3 = __ldcs(xr + u + 3);
                } else {
                    if (u >= 0     && u < T)     t0 = __ldcs(xr + u);
                    if (u + 1 >= 0 && u + 1 < T) t1 = __ldcs(xr + u + 1);
                    if (u + 2 >= 0 && u + 2 < T) t2 = __ldcs(xr + u + 2);
                    if (u + 3 >= 0 && u + 3 < T) t3 = __ldcs(xr + u + 3);
                }
            }
            v[k] = make_float4(t0, t1, t2, t3);
        }
#pragma unroll
        for (int k = 0; k < VEC; ++k) {
            const int w = tile0 + threadIdx.x + k * THREADS;
            if (w < T4)
                __stcs(out4 + wbase + w, v[k]);
        }
    }
}

extern "C" void kernel_launch(void* const* d_in, const int* in_sizes, int n_in,
                              void* d_out, int out_size) {
    const float* x      = (const float*)d_in[0];
    const int*   shifts = (const int*)d_in[1];
    float4*      out4   = (float4*)d_out;

    const int rows = in_sizes[1];            // B*M = 256
    const int T    = in_sizes[0] / rows;     // 160000
    const int T4   = T / 4;                  // 40000
    const int max_shift = T / 10;            // 16000

    dim3 grid((T4 + WPB - 1) / WPB, rows);   // (10, 256)
    random_shift_kernel<<<grid, THREADS>>>(x, shifts, out4, T, max_shift);
}

// round 16
// speedup vs baseline: 1.0142x; 1.0142x over previous
#include <cuda_runtime.h>

// out[row, t] = x[row, t - s]  if 0 <= t - s < T else 0
// rows = 256, T = 160000 (T % 4 == 0), s = shifts[row] - max_shift in [-16000, 16000]
//
// FINAL kernel (measured optimum over 15 rounds). Config: THREADS=512,
// VEC=4 float4 words per thread strided by blockDim, all loads front-batched
// before stores (MLP=4), streaming cache hints both sides (__ldcs/__stcs),
// interior tiles (~90%) skip all predication, full 5120-CTA launch.
//
// Exhausted-axis summary (all plateau at ~74% DRAM, ~5.88 TB/s, ~265 MB/iter):
//   - read alignment (misaligned scalar vs aligned f4+shuffle): neutral
//   - vector width 32/128/256-bit loads, 128/256-bit stores: 128b stores best
//   - MLP 1/4/8 words/thread: 4 saturates
//   - cache policies {default, cs, evict_last} x {default, cs}: cs/cs best
//   - L2 residency partitioning: inert without carveout
//   - persistent grid-stride: regresses (serializes MLP)
//   - TMA bulk read staging: neutral (DRAM path-independent)
//   - block size 256/512/1024: 512 best
// Remaining gap to 8 TB/s spec is mixed R/W DRAM turnaround efficiency.

#define VEC 4
#define THREADS 512
#define WPB (VEC * THREADS)   // 2048 float4 words = 8192 floats per tile

__global__ void __launch_bounds__(THREADS)
random_shift_kernel(const float* __restrict__ x,
                    const int* __restrict__ shifts,
                    float4* __restrict__ out4,
                    int T, int max_shift) {
    const int row = blockIdx.y;
    const int s = shifts[row] - max_shift;

    const int T4 = T >> 2;
    const int tile0 = blockIdx.x * WPB;                    // first word of tile
    const size_t ebase = (size_t)row * (size_t)T;          // element base
    const size_t wbase = (size_t)row * (size_t)T4;         // word base
    const float* __restrict__ xr = x + ebase;

    // tile source element range: [4*tile0 - s, 4*(tile0+WPB) - s)
    const int src_lo = 4 * tile0 - s;
    const int src_hi = 4 * (tile0 + WPB) - s;
    const bool interior = (src_lo >= 0) && (src_hi <= T) && (tile0 + WPB <= T4);

    float4 v[VEC];

    if (interior) {
#pragma unroll
        for (int k = 0; k < VEC; ++k) {
            const int u = 4 * (tile0 + (int)threadIdx.x + k * THREADS) - s;
            v[k].x = __ldcs(xr + u);
            v[k].y = __ldcs(xr + u + 1);
            v[k].z = __ldcs(xr + u + 2);
            v[k].w = __ldcs(xr + u + 3);
        }
#pragma unroll
        for (int k = 0; k < VEC; ++k) {
            const int w = tile0 + threadIdx.x + k * THREADS;
            __stcs(out4 + wbase + w, v[k]);
        }
    } else {
#pragma unroll
        for (int k = 0; k < VEC; ++k) {
            const int w = tile0 + threadIdx.x + k * THREADS;
            const int u = 4 * w - s;
            float t0 = 0.f, t1 = 0.f, t2 = 0.f, t3 = 0.f;
            if (w < T4) {
                if (u >= 0 && u + 3 < T) {
                    t0 = __ldcs(xr + u);
                    t1 = __ldcs(xr + u + 1);
                    t2 = __ldcs(xr + u + 2);
                    t3 = __ldcs(xr + u + 3);
                } else {
                    if (u >= 0     && u < T)     t0 = __ldcs(xr + u);
                    if (u + 1 >= 0 && u + 1 < T) t1 = __ldcs(xr + u + 1);
                    if (u + 2 >= 0 && u + 2 < T) t2 = __ldcs(xr + u + 2);
                    if (u + 3 >= 0 && u + 3 < T) t3 = __ldcs(xr + u + 3);
                }
            }
            v[k] = make_float4(t0, t1, t2, t3);
        }
#pragma unroll
        for (int k = 0; k < VEC; ++k) {
            const int w = tile0 + threadIdx.x + k * THREADS;
            if (w < T4)
                __stcs(out4 + wbase + w, v[k]);
        }
    }
}

extern "C" void kernel_launch(void* const* d_in, const int* in_sizes, int n_in,
                              void* d_out, int out_size) {
    const float* x      = (const float*)d_in[0];
    const int*   shifts = (const int*)d_in[1];
    float4*      out4   = (float4*)d_out;

    const int rows = in_sizes[1];            // B*M = 256
    const int T    = in_sizes[0] / rows;     // 160000
    const int T4   = T / 4;                  // 40000
    const int max_shift = T / 10;            // 16000

    dim3 grid((T4 + WPB - 1) / WPB, rows);   // (20, 256)
    random_shift_kernel<<<grid, THREADS>>>(x, shifts, out4, T, max_shift);
}